// round 3
// baseline (speedup 1.0000x reference)
#include <cuda_runtime.h>
#include <math.h>

// Problem constants (fixed by setup_inputs)
#define B_   4
#define N_   8192
#define M_   8192
#define KNN  16
#define C_   64
#define KS_  16
#define NBLK1 512          // blocks per batch for k1/k2 (16 points per block)
#define MK_INV (1.0f/((float)M_*(float)KNN))

// ---------------- device scratch (no allocation allowed) ----------------
__device__ float g_xt  [B_*N_*C_];        // x transposed: [B][N][64]
__device__ float g_post[B_*N_*4];         // pos transposed+padded: [B][N][4]
__device__ float g_dw  [B_*M_*KNN];       // distance weights [B][M][K]
__device__ float g_t1  [B_*M_*KS_*KNN];   // fc1 output [B][M][ch][K]
__device__ float g_t2  [B_*M_*KS_*KNN];   // fc2 output [B][M][ch][K]
__device__ float g_part1[B_*NBLK1*32];    // stats partials pass1
__device__ float g_part2[B_*NBLK1*32];    // stats partials pass2
__device__ float2 g_ab1[B_*KS_];          // fused scale/shift inorm1
__device__ float2 g_ab2[B_*KS_];          // fused scale/shift inorm2
__device__ float g_cvP [64*1024];         // repacked cv weights

// ---------------- prep kernels ----------------

// transpose x [B][64][N] -> g_xt [B][N][64]
__global__ void k_xt(const float* __restrict__ x) {
    __shared__ float tile[32][33];
    int b  = blockIdx.z;
    int c0 = blockIdx.y * 32;
    int n0 = blockIdx.x * 32;
    int tx = threadIdx.x, ty = threadIdx.y;   // 32 x 8
    #pragma unroll
    for (int i = 0; i < 32; i += 8)
        tile[ty + i][tx] = x[(size_t)(b*C_ + c0 + ty + i)*N_ + n0 + tx];
    __syncthreads();
    #pragma unroll
    for (int i = 0; i < 32; i += 8)
        g_xt[(size_t)(b*N_ + n0 + ty + i)*C_ + c0 + tx] = tile[tx][ty + i];
}

// transpose pos [B][3][N] -> g_post [B][N][4]
__global__ void k_pos(const float* __restrict__ pos) {
    int b = blockIdx.y;
    int n = blockIdx.x * 256 + threadIdx.x;
    float4 v;
    v.x = pos[(size_t)(b*3 + 0)*N_ + n];
    v.y = pos[(size_t)(b*3 + 1)*N_ + n];
    v.z = pos[(size_t)(b*3 + 2)*N_ + n];
    v.w = 0.0f;
    ((float4*)g_post)[b*N_ + n] = v;
}

// repack cv_w [o][c][j] into g_cvP[(dg*64+o)*4+e] where d'=dg*4+e = j*64+c
__global__ void k_cvp(const float* __restrict__ cv) {
    int g = blockIdx.x * 256 + threadIdx.x;  // 65536 total
    int o = g >> 10;
    int d = g & 1023;            // d' = j*64 + c
    int c = d & 63;
    int j = d >> 6;
    g_cvP[((d >> 2) * 64 + o) * 4 + (d & 3)] = cv[(size_t)(o*64 + c)*16 + j];
}

// ---------------- pass 1: pts, dw, t1 = fc1 @ (pts/nr), stats partials ----------------
// 256 threads = 16 points x 16 lanes (lane per neighbor k)
__global__ void k1(const float* __restrict__ sup, const int* __restrict__ nbr,
                   const float* __restrict__ alpha_p, const float* __restrict__ beta_p,
                   const float* __restrict__ nr_p, const float* __restrict__ fc1) {
    __shared__ float s_fc1[48];
    __shared__ float s_red[8*32];
    int t = threadIdx.x;
    if (t < 48) s_fc1[t] = fc1[t];
    __syncthreads();

    int b = blockIdx.y;
    int m = blockIdx.x * 16 + (t >> 4);
    int k = t & 15;
    float alpha = alpha_p[0], beta = beta_p[0], inr = 1.0f / nr_p[0];

    int n = nbr[(size_t)(b*M_ + m)*KNN + k];
    float4 p = ((const float4*)g_post)[b*N_ + n];
    float sx = sup[(size_t)(b*3 + 0)*M_ + m];
    float sy = sup[(size_t)(b*3 + 1)*M_ + m];
    float sz = sup[(size_t)(b*3 + 2)*M_ + m];
    float px = p.x - sx, py = p.y - sy, pz = p.z - sz;

    float d  = sqrtf(px*px + py*py + pz*pz);
    float sg = 1.0f / (1.0f + expf(alpha*d - beta));
    float ssum = sg;
    #pragma unroll
    for (int s = 8; s >= 1; s >>= 1) ssum += __shfl_xor_sync(0xffffffffu, ssum, s);
    float dws = ssum + ((ssum == 0.0f) ? 1.0f : 0.0f) + 1e-6f;
    float dwk = sg / dws * (float)KNN;
    g_dw[(size_t)(b*M_ + m)*KNN + k] = dwk;

    px *= inr; py *= inr; pz *= inr;
    size_t base = ((size_t)(b*M_ + m)*16)*16 + k;
    float stat[32];
    #pragma unroll
    for (int ch = 0; ch < 16; ch++) {
        float v = s_fc1[ch*3]*px + s_fc1[ch*3+1]*py + s_fc1[ch*3+2]*pz;
        g_t1[base + ch*16] = v;
        stat[ch] = v; stat[16+ch] = v*v;
    }
    // deterministic block reduce of 32 stat values
    int lane = t & 31, wid = t >> 5;
    #pragma unroll
    for (int i = 0; i < 32; i++) {
        float v = stat[i];
        #pragma unroll
        for (int s = 16; s >= 1; s >>= 1) v += __shfl_xor_sync(0xffffffffu, v, s);
        if (lane == 0) s_red[wid*32 + i] = v;
    }
    __syncthreads();
    if (t < 32) {
        float a = 0.0f;
        #pragma unroll
        for (int w = 0; w < 8; w++) a += s_red[w*32 + t];
        g_part1[((size_t)b*NBLK1 + blockIdx.x)*32 + t] = a;
    }
}

// ---------------- stats finalize: mean/var -> fused scale/shift ----------------
__global__ void k_stats(int which, const float* __restrict__ bnw, const float* __restrict__ bnb) {
    __shared__ float s[32];
    const float* part = which ? g_part2 : g_part1;
    float2* ab = which ? g_ab2 : g_ab1;
    int b = blockIdx.x, t = threadIdx.x;  // 32 threads
    float a = 0.0f;
    for (int r = 0; r < NBLK1; r++) a += part[((size_t)b*NBLK1 + r)*32 + t];
    s[t] = a;
    __syncthreads();
    if (t < 16) {
        float mean = s[t] * MK_INV;
        float var  = s[t+16] * MK_INV - mean*mean;
        float rstd = rsqrtf(var + 1e-5f);
        float sc = bnw[t] * rstd;
        ab[b*16 + t] = make_float2(sc, bnb[t] - mean*sc);
    }
}

// ---------------- pass 2: mat1 = relu(inorm(t1)), mp1, t2 = fc2@[mat1;mp1], stats ----------------
__global__ void k2(const float* __restrict__ fc2) {
    __shared__ float s_fc2[512];
    __shared__ float2 s_ab[16];
    __shared__ float s_red[8*32];
    int t = threadIdx.x, b = blockIdx.y;
    s_fc2[t] = fc2[t];
    s_fc2[t + 256] = fc2[t + 256];
    if (t < 16) s_ab[t] = g_ab1[b*16 + t];
    __syncthreads();

    int m = blockIdx.x * 16 + (t >> 4);
    int k = t & 15;
    float dwk = g_dw[(size_t)(b*M_ + m)*KNN + k];
    size_t base = ((size_t)(b*M_ + m)*16)*16 + k;

    float mat1[16], mp1[16];
    #pragma unroll
    for (int ch = 0; ch < 16; ch++) {
        float v = g_t1[base + ch*16];
        float2 a = s_ab[ch];
        v = fmaxf(fmaf(v, a.x, a.y), 0.0f);
        mat1[ch] = v;
        float w = v * dwk;
        #pragma unroll
        for (int s = 8; s >= 1; s >>= 1) w = fmaxf(w, __shfl_xor_sync(0xffffffffu, w, s));
        mp1[ch] = w;
    }
    float stat[32];
    #pragma unroll
    for (int j = 0; j < 16; j++) {
        float v = 0.0f;
        #pragma unroll
        for (int c = 0; c < 16; c++) v = fmaf(s_fc2[j*32 + c],      mat1[c], v);
        #pragma unroll
        for (int c = 0; c < 16; c++) v = fmaf(s_fc2[j*32 + 16 + c], mp1[c],  v);
        g_t2[base + j*16] = v;
        stat[j] = v; stat[16+j] = v*v;
    }
    int lane = t & 31, wid = t >> 5;
    #pragma unroll
    for (int i = 0; i < 32; i++) {
        float v = stat[i];
        #pragma unroll
        for (int s = 16; s >= 1; s >>= 1) v += __shfl_xor_sync(0xffffffffu, v, s);
        if (lane == 0) s_red[wid*32 + i] = v;
    }
    __syncthreads();
    if (t < 32) {
        float a = 0.0f;
        #pragma unroll
        for (int w = 0; w < 8; w++) a += s_red[w*32 + t];
        g_part2[((size_t)b*NBLK1 + blockIdx.x)*32 + t] = a;
    }
}

// ---------------- pass 3 (fused): mat3, gather+feat GEMM, cv GEMM ----------------
// 512 threads, 32 points per block.
// smem: s_feat 32768f | s_mat3 8192f | s_fc3 512f | s_ab 32f | s_idx 512i
#define K4_SMEM ((32768 + 8192 + 512 + 32) * 4 + 512 * 4)

__device__ __forceinline__ void fma4(float4& acc, const float4& xv, float s) {
    acc.x = fmaf(xv.x, s, acc.x);
    acc.y = fmaf(xv.y, s, acc.y);
    acc.z = fmaf(xv.z, s, acc.z);
    acc.w = fmaf(xv.w, s, acc.w);
}

__global__ void __launch_bounds__(512, 1)
k4(const int* __restrict__ nbr, const float* __restrict__ fc3, float* __restrict__ out) {
    extern __shared__ float sm[];
    float* s_feat = sm;                         // 32768 floats: [pt][d'=j*64+c]
    float* s_mat3 = sm + 32768;                 // 8192  floats: [pt][k][j]
    float* s_fc3  = sm + 32768 + 8192;          // 512
    float* s_ab   = sm + 32768 + 8192 + 512;    // 32: scale[16], shift[16]
    int*   s_idx  = (int*)(sm + 32768 + 8192 + 512 + 32); // 512

    int t = threadIdx.x, b = blockIdx.y;
    int m0 = blockIdx.x * 32;

    s_fc3[t] = fc3[t];
    s_idx[t] = nbr[((size_t)(b*M_) + m0)*KNN + t];
    if (t < 16) { float2 a = g_ab2[b*16 + t]; s_ab[t] = a.x; s_ab[16 + t] = a.y; }
    __syncthreads();

    // ---- phase 1: mat3[pt][k][j] ----
    {
        int pt = t >> 4, k = t & 15;
        int m = m0 + pt;
        float dwk = g_dw[(size_t)(b*M_ + m)*KNN + k];
        size_t base = ((size_t)(b*M_ + m)*16)*16 + k;
        float mat2[16], mp2[16];
        #pragma unroll
        for (int ch = 0; ch < 16; ch++) {
            float v = g_t2[base + ch*16];
            v = fmaxf(fmaf(v, s_ab[ch], s_ab[16 + ch]), 0.0f);
            mat2[ch] = v;
            float w = v * dwk;
            #pragma unroll
            for (int s = 8; s >= 1; s >>= 1) w = fmaxf(w, __shfl_xor_sync(0xffffffffu, w, s));
            mp2[ch] = w;
        }
        float t3[16];
        #pragma unroll
        for (int j = 0; j < 16; j++) {
            float v = 0.0f;
            #pragma unroll
            for (int c = 0; c < 16; c++) v = fmaf(s_fc3[j*32 + c],      mat2[c], v);
            #pragma unroll
            for (int c = 0; c < 16; c++) v = fmaf(s_fc3[j*32 + 16 + c], mp2[c],  v);
            t3[j] = fmaxf(v, 0.0f) * dwk;
        }
        float4* sm4 = (float4*)s_mat3;
        #pragma unroll
        for (int jg = 0; jg < 4; jg++)
            sm4[pt*64 + k*4 + jg] = make_float4(t3[jg*4], t3[jg*4+1], t3[jg*4+2], t3[jg*4+3]);
    }
    __syncthreads();

    // ---- phase 2: feat[pt][j*64+c] = sum_k x_g[c,k]*mat3[j,k] ----
    {
        int pt = t >> 4, cg = t & 15;           // 4 channels per thread
        float4 facc[16];
        #pragma unroll
        for (int j = 0; j < 16; j++) facc[j] = make_float4(0.f, 0.f, 0.f, 0.f);
        const float4* xt4 = (const float4*)g_xt;
        const float4* sm4 = (const float4*)s_mat3;
        #pragma unroll
        for (int k = 0; k < 16; k++) {
            int n = s_idx[pt*16 + k];
            float4 xv = xt4[(size_t)(b*N_ + n)*16 + cg];
            #pragma unroll
            for (int jg = 0; jg < 4; jg++) {
                float4 mv = sm4[pt*64 + k*4 + jg];
                fma4(facc[jg*4 + 0], xv, mv.x);
                fma4(facc[jg*4 + 1], xv, mv.y);
                fma4(facc[jg*4 + 2], xv, mv.z);
                fma4(facc[jg*4 + 3], xv, mv.w);
            }
        }
        float4* sf4 = (float4*)s_feat;
        #pragma unroll
        for (int j = 0; j < 16; j++)
            sf4[pt*256 + j*16 + cg] = facc[j];
    }
    __syncthreads();

    // ---- phase 3: out[o][pt] = dot(cvP[o], feat[pt]) over 1024 ----
    {
        int o = t & 63, pg = t >> 6;
        int p0 = pg * 4;
        const float4* cv4 = (const float4*)g_cvP;
        const float4* sf4 = (const float4*)s_feat;
        float a0 = 0.f, a1 = 0.f, a2 = 0.f, a3 = 0.f;
        const float4* wp = cv4 + o;
        const float4* fp = sf4 + (size_t)p0 * 256;
        #pragma unroll 4
        for (int dg = 0; dg < 256; dg++) {
            float4 w  = wp[dg*64];
            float4 f0 = fp[dg];
            float4 f1 = fp[256 + dg];
            float4 f2 = fp[512 + dg];
            float4 f3 = fp[768 + dg];
            a0 = fmaf(w.x, f0.x, a0); a0 = fmaf(w.y, f0.y, a0);
            a0 = fmaf(w.z, f0.z, a0); a0 = fmaf(w.w, f0.w, a0);
            a1 = fmaf(w.x, f1.x, a1); a1 = fmaf(w.y, f1.y, a1);
            a1 = fmaf(w.z, f1.z, a1); a1 = fmaf(w.w, f1.w, a1);
            a2 = fmaf(w.x, f2.x, a2); a2 = fmaf(w.y, f2.y, a2);
            a2 = fmaf(w.z, f2.z, a2); a2 = fmaf(w.w, f2.w, a2);
            a3 = fmaf(w.x, f3.x, a3); a3 = fmaf(w.y, f3.y, a3);
            a3 = fmaf(w.z, f3.z, a3); a3 = fmaf(w.w, f3.w, a3);
        }
        size_t oidx = (((size_t)b*64 + o)*M_ + m0 + p0) >> 2;
        ((float4*)out)[oidx] = make_float4(a0, a1, a2, a3);
    }
}

// ---------------- launch ----------------
extern "C" void kernel_launch(void* const* d_in, const int* in_sizes, int n_in,
                              void* d_out, int out_size) {
    const float* x     = (const float*)d_in[0];
    const float* pos   = (const float*)d_in[1];
    const float* sup   = (const float*)d_in[2];
    const int*   nbr   = (const int*)  d_in[3];
    const float* alpha = (const float*)d_in[4];
    const float* beta  = (const float*)d_in[5];
    const float* nr    = (const float*)d_in[6];
    const float* fc1   = (const float*)d_in[7];
    const float* fc2   = (const float*)d_in[8];
    const float* fc3   = (const float*)d_in[9];
    const float* bn1w  = (const float*)d_in[10];
    const float* bn1b  = (const float*)d_in[11];
    const float* bn2w  = (const float*)d_in[12];
    const float* bn2b  = (const float*)d_in[13];
    const float* cvw   = (const float*)d_in[14];
    float* out = (float*)d_out;

    cudaFuncSetAttribute((const void*)k4, cudaFuncAttributeMaxDynamicSharedMemorySize, K4_SMEM);

    k_xt  <<<dim3(N_/32, C_/32, B_), dim3(32, 8)>>>(x);
    k_pos <<<dim3(N_/256, B_), 256>>>(pos);
    k_cvp <<<256, 256>>>(cvw);
    k1    <<<dim3(NBLK1, B_), 256>>>(sup, nbr, alpha, beta, nr, fc1);
    k_stats<<<B_, 32>>>(0, bn1w, bn1b);
    k2    <<<dim3(NBLK1, B_), 256>>>(fc2);
    k_stats<<<B_, 32>>>(1, bn2w, bn2b);
    k4    <<<dim3(M_/32, B_), 512, K4_SMEM>>>(nbr, fc3, out);
}

// round 4
// speedup vs baseline: 1.1741x; 1.1741x over previous
#include <cuda_runtime.h>
#include <math.h>

// Problem constants (fixed by setup_inputs)
#define B_   4
#define N_   8192
#define M_   8192
#define KNN  16
#define C_   64
#define NBLK1 512
#define MK_INV (1.0f/((float)M_*(float)KNN))
#define FS4  257   // padded feat row stride in float4 (1028 floats)

// ---------------- device scratch ----------------
__device__ float  g_xt  [B_*N_*C_];        // x transposed: [B][N][64]
__device__ float  g_post[B_*N_*4];         // pos transposed+padded
__device__ float4 g_pts [B_*M_*KNN];       // normalized pts per neighbor
__device__ float  g_dw  [B_*M_*KNN];       // distance weights
__device__ float  g_t2  [(size_t)B_*M_*256]; // fc2 out, layout [b][m][k][j]
__device__ float  g_part1[B_*NBLK1*16];    // 9 moments partials (padded 16)
__device__ float  g_part2[B_*NBLK1*32];    // 32 stats partials
__device__ float2 g_ab1[B_*16];
__device__ float2 g_ab2[B_*16];
__device__ float  g_cvP[64*1024];          // cv repacked [o][d], d=j*64+c

// ---------------- prep kernels ----------------
__global__ void k_xt(const float* __restrict__ x) {
    __shared__ float tile[32][33];
    int b  = blockIdx.z;
    int c0 = blockIdx.y * 32;
    int n0 = blockIdx.x * 32;
    int tx = threadIdx.x, ty = threadIdx.y;   // 32 x 8
    #pragma unroll
    for (int i = 0; i < 32; i += 8)
        tile[ty + i][tx] = x[(size_t)(b*C_ + c0 + ty + i)*N_ + n0 + tx];
    __syncthreads();
    #pragma unroll
    for (int i = 0; i < 32; i += 8)
        g_xt[(size_t)(b*N_ + n0 + ty + i)*C_ + c0 + tx] = tile[tx][ty + i];
}

__global__ void k_pos(const float* __restrict__ pos) {
    int b = blockIdx.y;
    int n = blockIdx.x * 256 + threadIdx.x;
    float4 v;
    v.x = pos[(size_t)(b*3 + 0)*N_ + n];
    v.y = pos[(size_t)(b*3 + 1)*N_ + n];
    v.z = pos[(size_t)(b*3 + 2)*N_ + n];
    v.w = 0.0f;
    ((float4*)g_post)[b*N_ + n] = v;
}

// cv2[o][d] with d = j*64 + c
__global__ void k_cvp(const float* __restrict__ cv) {
    int g = blockIdx.x * 256 + threadIdx.x;  // 65536
    int o = g >> 10;
    int d = g & 1023;
    int c = d & 63;
    int j = d >> 6;
    g_cvP[g] = cv[(size_t)(o*64 + c)*16 + j];
}

// ---------------- pass 1: pts, dw, 9 raw moments ----------------
__global__ void k1(const float* __restrict__ sup, const int* __restrict__ nbr,
                   const float* __restrict__ alpha_p, const float* __restrict__ beta_p,
                   const float* __restrict__ nr_p) {
    __shared__ float s_red[8*9];
    int t = threadIdx.x;
    int b = blockIdx.y;
    int m = blockIdx.x * 16 + (t >> 4);
    int k = t & 15;
    float alpha = alpha_p[0], beta = beta_p[0], inr = 1.0f / nr_p[0];

    int n = nbr[(size_t)(b*M_ + m)*KNN + k];
    float4 p = ((const float4*)g_post)[b*N_ + n];
    float sx = sup[(size_t)(b*3 + 0)*M_ + m];
    float sy = sup[(size_t)(b*3 + 1)*M_ + m];
    float sz = sup[(size_t)(b*3 + 2)*M_ + m];
    float px = p.x - sx, py = p.y - sy, pz = p.z - sz;

    float d  = sqrtf(px*px + py*py + pz*pz);
    float sg = 1.0f / (1.0f + expf(alpha*d - beta));
    float ssum = sg;
    #pragma unroll
    for (int s = 8; s >= 1; s >>= 1) ssum += __shfl_xor_sync(0xffffffffu, ssum, s);
    float dws = ssum + ((ssum == 0.0f) ? 1.0f : 0.0f) + 1e-6f;
    float dwk = sg / dws * (float)KNN;
    g_dw[(size_t)(b*M_ + m)*KNN + k] = dwk;

    px *= inr; py *= inr; pz *= inr;
    g_pts[(size_t)(b*M_ + m)*KNN + k] = make_float4(px, py, pz, 0.0f);

    float mom[9];
    mom[0]=px; mom[1]=py; mom[2]=pz;
    mom[3]=px*px; mom[4]=py*py; mom[5]=pz*pz;
    mom[6]=px*py; mom[7]=px*pz; mom[8]=py*pz;

    int lane = t & 31, wid = t >> 5;
    #pragma unroll
    for (int i = 0; i < 9; i++) {
        float v = mom[i];
        #pragma unroll
        for (int s = 16; s >= 1; s >>= 1) v += __shfl_xor_sync(0xffffffffu, v, s);
        if (lane == 0) s_red[wid*9 + i] = v;
    }
    __syncthreads();
    if (t < 9) {
        float a = 0.0f;
        #pragma unroll
        for (int w = 0; w < 8; w++) a += s_red[w*9 + t];
        g_part1[((size_t)b*NBLK1 + blockIdx.x)*16 + t] = a;
    }
}

// ---------------- stats1: analytic per-channel mean/var from moments ----------------
__global__ void k_stats1(const float* __restrict__ fc1,
                         const float* __restrict__ bnw, const float* __restrict__ bnb) {
    __shared__ float s_w[16];
    __shared__ float s_m[9];
    int b = blockIdx.x, t = threadIdx.x;   // 512 threads
    int lane = t & 31, wid = t >> 5;
    float v[9];
    #pragma unroll
    for (int i = 0; i < 9; i++) v[i] = g_part1[((size_t)b*NBLK1 + t)*16 + i];
    #pragma unroll
    for (int i = 0; i < 9; i++) {
        float r = v[i];
        #pragma unroll
        for (int s = 16; s >= 1; s >>= 1) r += __shfl_xor_sync(0xffffffffu, r, s);
        if (lane == 0) s_w[wid] = r;
        __syncthreads();
        if (t == 0) {
            float a = 0.0f;
            #pragma unroll
            for (int w = 0; w < 16; w++) a += s_w[w];
            s_m[i] = a * MK_INV;
        }
        __syncthreads();
    }
    if (t < 16) {
        float w0 = fc1[t*3], w1 = fc1[t*3+1], w2 = fc1[t*3+2];
        float mean = w0*s_m[0] + w1*s_m[1] + w2*s_m[2];
        float ev2  = w0*w0*s_m[3] + w1*w1*s_m[4] + w2*w2*s_m[5]
                   + 2.0f*(w0*w1*s_m[6] + w0*w2*s_m[7] + w1*w2*s_m[8]);
        float var  = ev2 - mean*mean;
        float rstd = rsqrtf(var + 1e-5f);
        float sc = bnw[t] * rstd;
        g_ab1[b*16 + t] = make_float2(sc, bnb[t] - mean*sc);
    }
}

// ---------------- pass 2: recompute t1, mat1, mp1, t2 = fc2@[mat1;mp1], stats ----------------
__global__ void k2(const float* __restrict__ fc1, const float* __restrict__ fc2) {
    __shared__ float s_fc1[64];       // padded [ch][4]
    __shared__ float s_fc2[512];
    __shared__ float2 s_ab[16];
    __shared__ float s_red[8*32];
    int t = threadIdx.x, b = blockIdx.y;
    s_fc2[t] = fc2[t];
    s_fc2[t + 256] = fc2[t + 256];
    if (t < 16) {
        s_fc1[t*4+0] = fc1[t*3+0];
        s_fc1[t*4+1] = fc1[t*3+1];
        s_fc1[t*4+2] = fc1[t*3+2];
        s_fc1[t*4+3] = 0.0f;
        s_ab[t] = g_ab1[b*16 + t];
    }
    __syncthreads();

    int m = blockIdx.x * 16 + (t >> 4);
    int k = t & 15;
    float4 p = g_pts[(size_t)(b*M_ + m)*KNN + k];
    float dwk = g_dw[(size_t)(b*M_ + m)*KNN + k];

    float mat1[16], mp1[16];
    const float4* f1 = (const float4*)s_fc1;
    #pragma unroll
    for (int ch = 0; ch < 16; ch++) {
        float4 w = f1[ch];
        float v = w.x*p.x + w.y*p.y + w.z*p.z;
        float2 a = s_ab[ch];
        v = fmaxf(fmaf(v, a.x, a.y), 0.0f);
        mat1[ch] = v;
        float wmax = v * dwk;
        #pragma unroll
        for (int s = 8; s >= 1; s >>= 1) wmax = fmaxf(wmax, __shfl_xor_sync(0xffffffffu, wmax, s));
        mp1[ch] = wmax;
    }

    float t2v[16];
    const float4* f2 = (const float4*)s_fc2;
    #pragma unroll 4
    for (int j = 0; j < 16; j++) {
        float v = 0.0f;
        #pragma unroll
        for (int cq = 0; cq < 4; cq++) {
            float4 w = f2[j*8 + cq];
            v = fmaf(w.x, mat1[cq*4+0], v); v = fmaf(w.y, mat1[cq*4+1], v);
            v = fmaf(w.z, mat1[cq*4+2], v); v = fmaf(w.w, mat1[cq*4+3], v);
        }
        #pragma unroll
        for (int cq = 0; cq < 4; cq++) {
            float4 w = f2[j*8 + 4 + cq];
            v = fmaf(w.x, mp1[cq*4+0], v); v = fmaf(w.y, mp1[cq*4+1], v);
            v = fmaf(w.z, mp1[cq*4+2], v); v = fmaf(w.w, mp1[cq*4+3], v);
        }
        t2v[j] = v;
    }
    // store t2 layout [b][m][k][j]: 4 contiguous float4 per thread
    float4* o4 = (float4*)(g_t2 + (((size_t)(b*M_ + m)*16) + k)*16);
    o4[0] = make_float4(t2v[0], t2v[1], t2v[2], t2v[3]);
    o4[1] = make_float4(t2v[4], t2v[5], t2v[6], t2v[7]);
    o4[2] = make_float4(t2v[8], t2v[9], t2v[10], t2v[11]);
    o4[3] = make_float4(t2v[12], t2v[13], t2v[14], t2v[15]);

    float stat[32];
    #pragma unroll
    for (int j = 0; j < 16; j++) { stat[j] = t2v[j]; stat[16+j] = t2v[j]*t2v[j]; }
    int lane = t & 31, wid = t >> 5;
    #pragma unroll
    for (int i = 0; i < 32; i++) {
        float v = stat[i];
        #pragma unroll
        for (int s = 16; s >= 1; s >>= 1) v += __shfl_xor_sync(0xffffffffu, v, s);
        if (lane == 0) s_red[wid*32 + i] = v;
    }
    __syncthreads();
    if (t < 32) {
        float a = 0.0f;
        #pragma unroll
        for (int w = 0; w < 8; w++) a += s_red[w*32 + t];
        g_part2[((size_t)b*NBLK1 + blockIdx.x)*32 + t] = a;
    }
}

// ---------------- stats2: parallel reduction of 32 stats ----------------
__global__ void k_stats2(const float* __restrict__ bnw, const float* __restrict__ bnb) {
    __shared__ float s_p[32*32];
    __shared__ float s_c[32];
    int b = blockIdx.x, t = threadIdx.x;   // 1024 threads
    int w = t >> 5, s = t & 31;
    float a = 0.0f;
    #pragma unroll
    for (int i = 0; i < 16; i++)
        a += g_part2[((size_t)b*NBLK1 + w*16 + i)*32 + s];
    s_p[w*32 + s] = a;
    __syncthreads();
    if (t < 32) {
        float r = 0.0f;
        #pragma unroll
        for (int w2 = 0; w2 < 32; w2++) r += s_p[w2*32 + t];
        s_c[t] = r;
    }
    __syncthreads();
    if (t < 16) {
        float mean = s_c[t] * MK_INV;
        float var  = s_c[t+16] * MK_INV - mean*mean;
        float rstd = rsqrtf(var + 1e-5f);
        float sc = bnw[t] * rstd;
        g_ab2[b*16 + t] = make_float2(sc, bnb[t] - mean*sc);
    }
}

// ---------------- pass 3 (fused): mat3, gather+feat GEMM, cv GEMM ----------------
// 512 threads, 32 points per block.
// smem floats: s_feat 32*FS4*4=32896 | s_mat3 8192 | s_fc3 512 | s_ab 32 | s_idx 512i
#define K4_SMEM ((32896 + 8192 + 512 + 32 + 512) * 4)

__device__ __forceinline__ void fma4(float4& acc, const float4& xv, float s) {
    acc.x = fmaf(xv.x, s, acc.x);
    acc.y = fmaf(xv.y, s, acc.y);
    acc.z = fmaf(xv.z, s, acc.z);
    acc.w = fmaf(xv.w, s, acc.w);
}

__global__ void __launch_bounds__(512, 1)
k4(const int* __restrict__ nbr, const float* __restrict__ fc3, float* __restrict__ out) {
    extern __shared__ float sm[];
    float* s_feat = sm;                          // 32896 floats (32 rows x 1028)
    float* s_mat3 = sm + 32896;                  // 8192 (also reused as s_fin)
    float* s_fc3  = sm + 32896 + 8192;           // 512
    float* s_ab   = sm + 32896 + 8192 + 512;     // 32
    int*   s_idx  = (int*)(sm + 32896 + 8192 + 512 + 32); // 512

    int t = threadIdx.x, b = blockIdx.y;
    int m0 = blockIdx.x * 32;

    s_fc3[t] = fc3[t];
    s_idx[t] = nbr[((size_t)(b*M_) + m0)*KNN + t];
    if (t < 16) { float2 a = g_ab2[b*16 + t]; s_ab[t] = a.x; s_ab[16 + t] = a.y; }
    __syncthreads();

    // ---- phase 1: mat3[pt][k][j] ----
    {
        int pt = t >> 4, k = t & 15;
        int m = m0 + pt;
        float dwk = g_dw[(size_t)(b*M_ + m)*KNN + k];
        const float4* t24 = (const float4*)(g_t2 + (((size_t)(b*M_ + m)*16) + k)*16);
        float4 q0 = t24[0], q1 = t24[1], q2 = t24[2], q3 = t24[3];
        float mat2[16], mp2[16];
        mat2[0]=q0.x; mat2[1]=q0.y; mat2[2]=q0.z; mat2[3]=q0.w;
        mat2[4]=q1.x; mat2[5]=q1.y; mat2[6]=q1.z; mat2[7]=q1.w;
        mat2[8]=q2.x; mat2[9]=q2.y; mat2[10]=q2.z; mat2[11]=q2.w;
        mat2[12]=q3.x; mat2[13]=q3.y; mat2[14]=q3.z; mat2[15]=q3.w;
        #pragma unroll
        for (int ch = 0; ch < 16; ch++) {
            float v = fmaxf(fmaf(mat2[ch], s_ab[ch], s_ab[16 + ch]), 0.0f);
            mat2[ch] = v;
            float w = v * dwk;
            #pragma unroll
            for (int s = 8; s >= 1; s >>= 1) w = fmaxf(w, __shfl_xor_sync(0xffffffffu, w, s));
            mp2[ch] = w;
        }
        const float4* f3 = (const float4*)s_fc3;
        float t3[16];
        #pragma unroll 4
        for (int j = 0; j < 16; j++) {
            float v = 0.0f;
            #pragma unroll
            for (int cq = 0; cq < 4; cq++) {
                float4 w = f3[j*8 + cq];
                v = fmaf(w.x, mat2[cq*4+0], v); v = fmaf(w.y, mat2[cq*4+1], v);
                v = fmaf(w.z, mat2[cq*4+2], v); v = fmaf(w.w, mat2[cq*4+3], v);
            }
            #pragma unroll
            for (int cq = 0; cq < 4; cq++) {
                float4 w = f3[j*8 + 4 + cq];
                v = fmaf(w.x, mp2[cq*4+0], v); v = fmaf(w.y, mp2[cq*4+1], v);
                v = fmaf(w.z, mp2[cq*4+2], v); v = fmaf(w.w, mp2[cq*4+3], v);
            }
            t3[j] = fmaxf(v, 0.0f) * dwk;
        }
        float4* sm4 = (float4*)s_mat3;
        #pragma unroll
        for (int jg = 0; jg < 4; jg++)
            sm4[pt*64 + k*4 + jg] = make_float4(t3[jg*4], t3[jg*4+1], t3[jg*4+2], t3[jg*4+3]);
    }
    __syncthreads();

    // ---- phase 2: feat[pt][d = j*64 + c] ----
    {
        int pt = t >> 4, cg = t & 15;           // 4 channels per thread
        float4 facc[16];
        #pragma unroll
        for (int j = 0; j < 16; j++) facc[j] = make_float4(0.f, 0.f, 0.f, 0.f);
        const float4* xt4 = (const float4*)g_xt;
        const float4* sm4 = (const float4*)s_mat3;
        #pragma unroll 4
        for (int k = 0; k < 16; k++) {
            int n = s_idx[pt*16 + k];
            float4 xv = xt4[(size_t)(b*N_ + n)*16 + cg];
            #pragma unroll
            for (int jg = 0; jg < 4; jg++) {
                float4 mv = sm4[pt*64 + k*4 + jg];
                fma4(facc[jg*4 + 0], xv, mv.x);
                fma4(facc[jg*4 + 1], xv, mv.y);
                fma4(facc[jg*4 + 2], xv, mv.z);
                fma4(facc[jg*4 + 3], xv, mv.w);
            }
        }
        float4* sf4 = (float4*)s_feat;
        #pragma unroll
        for (int j = 0; j < 16; j++)
            sf4[pt*FS4 + j*16 + cg] = facc[j];
    }
    __syncthreads();

    // ---- phase 3: out[o][p] = dot(cv2[o], feat[p]) over d=1024, lane-over-d ----
    {
        int warp = t >> 5, lane = t & 31;
        int g    = warp >> 2;                   // o group base
        int pbase = (warp & 3) * 8;             // 8 points per warp
        const float4* cv4 = (const float4*)g_cvP;
        const float4* sf4 = (const float4*)s_feat;
        float* s_fin = s_mat3;                  // reuse: [o][p] 64x32

        #pragma unroll 1
        for (int it = 0; it < 4; it++) {
            int obase = g*4 + it*16;
            float acc[4][8];
            #pragma unroll
            for (int oi = 0; oi < 4; oi++)
                #pragma unroll
                for (int pi = 0; pi < 8; pi++) acc[oi][pi] = 0.0f;

            #pragma unroll 2
            for (int s = 0; s < 8; s++) {
                float4 wv[4], fv[8];
                #pragma unroll
                for (int oi = 0; oi < 4; oi++)
                    wv[oi] = cv4[(obase + oi)*256 + s*32 + lane];
                #pragma unroll
                for (int pi = 0; pi < 8; pi++)
                    fv[pi] = sf4[(pbase + pi)*FS4 + s*32 + lane];
                #pragma unroll
                for (int oi = 0; oi < 4; oi++)
                    #pragma unroll
                    for (int pi = 0; pi < 8; pi++) {
                        acc[oi][pi] = fmaf(wv[oi].x, fv[pi].x, acc[oi][pi]);
                        acc[oi][pi] = fmaf(wv[oi].y, fv[pi].y, acc[oi][pi]);
                        acc[oi][pi] = fmaf(wv[oi].z, fv[pi].z, acc[oi][pi]);
                        acc[oi][pi] = fmaf(wv[oi].w, fv[pi].w, acc[oi][pi]);
                    }
            }
            // butterfly reduce each acc across lanes, one lane stores each
            #pragma unroll
            for (int oi = 0; oi < 4; oi++)
                #pragma unroll
                for (int pi = 0; pi < 8; pi++) {
                    float v = acc[oi][pi];
                    #pragma unroll
                    for (int s = 16; s >= 1; s >>= 1) v += __shfl_xor_sync(0xffffffffu, v, s);
                    if (lane == oi*8 + pi)
                        s_fin[(obase + oi)*32 + pbase + pi] = v;
                }
        }
    }
    __syncthreads();

    // coalesced output write
    {
        int o = t >> 3, pq = t & 7;
        float4 v = ((const float4*)s_mat3)[o*8 + pq];
        ((float4*)out)[((size_t)(b*64 + o))*2048 + (m0 >> 2) + pq] = v;
    }
}

// ---------------- launch ----------------
extern "C" void kernel_launch(void* const* d_in, const int* in_sizes, int n_in,
                              void* d_out, int out_size) {
    const float* x     = (const float*)d_in[0];
    const float* pos   = (const float*)d_in[1];
    const float* sup   = (const float*)d_in[2];
    const int*   nbr   = (const int*)  d_in[3];
    const float* alpha = (const float*)d_in[4];
    const float* beta  = (const float*)d_in[5];
    const float* nr    = (const float*)d_in[6];
    const float* fc1   = (const float*)d_in[7];
    const float* fc2   = (const float*)d_in[8];
    const float* fc3   = (const float*)d_in[9];
    const float* bn1w  = (const float*)d_in[10];
    const float* bn1b  = (const float*)d_in[11];
    const float* bn2w  = (const float*)d_in[12];
    const float* bn2b  = (const float*)d_in[13];
    const float* cvw   = (const float*)d_in[14];
    float* out = (float*)d_out;

    cudaFuncSetAttribute((const void*)k4, cudaFuncAttributeMaxDynamicSharedMemorySize, K4_SMEM);

    k_xt    <<<dim3(N_/32, C_/32, B_), dim3(32, 8)>>>(x);
    k_pos   <<<dim3(N_/256, B_), 256>>>(pos);
    k_cvp   <<<256, 256>>>(cvw);
    k1      <<<dim3(NBLK1, B_), 256>>>(sup, nbr, alpha, beta, nr);
    k_stats1<<<B_, 512>>>(fc1, bn1w, bn1b);
    k2      <<<dim3(NBLK1, B_), 256>>>(fc1, fc2);
    k_stats2<<<B_, 1024>>>(bn2w, bn2b);
    k4      <<<dim3(M_/32, B_), 512, K4_SMEM>>>(nbr, fc3, out);
}

// round 7
// speedup vs baseline: 1.2065x; 1.0276x over previous
#include <cuda_runtime.h>
#include <stdint.h>
#include <math.h>

// Problem constants (fixed by setup_inputs)
#define B_   4
#define N_   8192
#define M_   8192
#define KNN  16
#define C_   64
#define NBLK1 512
#define MK_INV (1.0f/((float)M_*(float)KNN))
#define FS4  257   // padded feat row stride in float4 (1028 floats)

typedef unsigned long long ull;

// ---------------- packed f32x2 helpers (Blackwell base ISA) ----------------
__device__ __forceinline__ ull fma2(ull a, ull b, ull c) {
    ull d;
    asm("fma.rn.f32x2 %0, %1, %2, %3;" : "=l"(d) : "l"(a), "l"(b), "l"(c));
    return d;
}
__device__ __forceinline__ ull dup2(float x) {
    ull r;
    asm("mov.b64 %0, {%1, %2};" : "=l"(r) : "f"(x), "f"(x));
    return r;
}
__device__ __forceinline__ float2 unpack2(ull v) {
    float2 f;
    asm("mov.b64 {%0, %1}, %2;" : "=f"(f.x), "=f"(f.y) : "l"(v));
    return f;
}

// ---------------- device scratch ----------------
__device__ float  g_xt  [B_*N_*C_];        // x transposed: [B][N][64]
__device__ float  g_post[B_*N_*4];         // pos transposed+padded
__device__ float4 g_pts [B_*M_*KNN];       // normalized pts per neighbor
__device__ float  g_dw  [B_*M_*KNN];       // distance weights
__device__ float  g_t2  [(size_t)B_*M_*256]; // fc2 out, layout [b][m][k][j]
__device__ float  g_part1[B_*NBLK1*16];
__device__ float  g_part2[B_*NBLK1*32];
__device__ float2 g_ab1[B_*16];
__device__ float2 g_ab2[B_*16];
__device__ __align__(16) float g_cvP[64*1024];  // cv repacked [o][d], d=j*64+c

// ---------------- prep kernels ----------------
__global__ void k_xt(const float* __restrict__ x) {
    __shared__ float tile[32][33];
    int b  = blockIdx.z;
    int c0 = blockIdx.y * 32;
    int n0 = blockIdx.x * 32;
    int tx = threadIdx.x, ty = threadIdx.y;   // 32 x 8
    #pragma unroll
    for (int i = 0; i < 32; i += 8)
        tile[ty + i][tx] = x[(size_t)(b*C_ + c0 + ty + i)*N_ + n0 + tx];
    __syncthreads();
    #pragma unroll
    for (int i = 0; i < 32; i += 8)
        g_xt[(size_t)(b*N_ + n0 + ty + i)*C_ + c0 + tx] = tile[tx][ty + i];
}

__global__ void k_pos(const float* __restrict__ pos) {
    int b = blockIdx.y;
    int n = blockIdx.x * 256 + threadIdx.x;
    float4 v;
    v.x = pos[(size_t)(b*3 + 0)*N_ + n];
    v.y = pos[(size_t)(b*3 + 1)*N_ + n];
    v.z = pos[(size_t)(b*3 + 2)*N_ + n];
    v.w = 0.0f;
    ((float4*)g_post)[b*N_ + n] = v;
}

// cv2[o][d] with d = j*64 + c
__global__ void k_cvp(const float* __restrict__ cv) {
    int g = blockIdx.x * 256 + threadIdx.x;  // 65536
    int o = g >> 10;
    int d = g & 1023;
    int c = d & 63;
    int j = d >> 6;
    g_cvP[g] = cv[(size_t)(o*64 + c)*16 + j];
}

// ---------------- pass 1: pts, dw, 9 raw moments ----------------
__global__ void k1(const float* __restrict__ sup, const int* __restrict__ nbr,
                   const float* __restrict__ alpha_p, const float* __restrict__ beta_p,
                   const float* __restrict__ nr_p) {
    __shared__ float s_red[8*9];
    int t = threadIdx.x;
    int b = blockIdx.y;
    int m = blockIdx.x * 16 + (t >> 4);
    int k = t & 15;
    float alpha = alpha_p[0], beta = beta_p[0], inr = 1.0f / nr_p[0];

    int n = nbr[(size_t)(b*M_ + m)*KNN + k];
    float4 p = ((const float4*)g_post)[b*N_ + n];
    float sx = sup[(size_t)(b*3 + 0)*M_ + m];
    float sy = sup[(size_t)(b*3 + 1)*M_ + m];
    float sz = sup[(size_t)(b*3 + 2)*M_ + m];
    float px = p.x - sx, py = p.y - sy, pz = p.z - sz;

    float d  = sqrtf(px*px + py*py + pz*pz);
    float sg = 1.0f / (1.0f + expf(alpha*d - beta));
    float ssum = sg;
    #pragma unroll
    for (int s = 8; s >= 1; s >>= 1) ssum += __shfl_xor_sync(0xffffffffu, ssum, s);
    float dws = ssum + ((ssum == 0.0f) ? 1.0f : 0.0f) + 1e-6f;
    float dwk = sg / dws * (float)KNN;
    g_dw[(size_t)(b*M_ + m)*KNN + k] = dwk;

    px *= inr; py *= inr; pz *= inr;
    g_pts[(size_t)(b*M_ + m)*KNN + k] = make_float4(px, py, pz, 0.0f);

    float mom[9];
    mom[0]=px; mom[1]=py; mom[2]=pz;
    mom[3]=px*px; mom[4]=py*py; mom[5]=pz*pz;
    mom[6]=px*py; mom[7]=px*pz; mom[8]=py*pz;

    int lane = t & 31, wid = t >> 5;
    #pragma unroll
    for (int i = 0; i < 9; i++) {
        float v = mom[i];
        #pragma unroll
        for (int s = 16; s >= 1; s >>= 1) v += __shfl_xor_sync(0xffffffffu, v, s);
        if (lane == 0) s_red[wid*9 + i] = v;
    }
    __syncthreads();
    if (t < 9) {
        float a = 0.0f;
        #pragma unroll
        for (int w = 0; w < 8; w++) a += s_red[w*9 + t];
        g_part1[((size_t)b*NBLK1 + blockIdx.x)*16 + t] = a;
    }
}

// ---------------- stats1: analytic per-channel mean/var from moments ----------------
__global__ void k_stats1(const float* __restrict__ fc1,
                         const float* __restrict__ bnw, const float* __restrict__ bnb) {
    __shared__ float s_w[16];
    __shared__ float s_m[9];
    int b = blockIdx.x, t = threadIdx.x;   // 512 threads
    int lane = t & 31, wid = t >> 5;
    float v[9];
    #pragma unroll
    for (int i = 0; i < 9; i++) v[i] = g_part1[((size_t)b*NBLK1 + t)*16 + i];
    #pragma unroll
    for (int i = 0; i < 9; i++) {
        float r = v[i];
        #pragma unroll
        for (int s = 16; s >= 1; s >>= 1) r += __shfl_xor_sync(0xffffffffu, r, s);
        if (lane == 0) s_w[wid] = r;
        __syncthreads();
        if (t == 0) {
            float a = 0.0f;
            #pragma unroll
            for (int w = 0; w < 16; w++) a += s_w[w];
            s_m[i] = a * MK_INV;
        }
        __syncthreads();
    }
    if (t < 16) {
        float w0 = fc1[t*3], w1 = fc1[t*3+1], w2 = fc1[t*3+2];
        float mean = w0*s_m[0] + w1*s_m[1] + w2*s_m[2];
        float ev2  = w0*w0*s_m[3] + w1*w1*s_m[4] + w2*w2*s_m[5]
                   + 2.0f*(w0*w1*s_m[6] + w0*w2*s_m[7] + w1*w2*s_m[8]);
        float var  = ev2 - mean*mean;
        float rstd = rsqrtf(var + 1e-5f);
        float sc = bnw[t] * rstd;
        g_ab1[b*16 + t] = make_float2(sc, bnb[t] - mean*sc);
    }
}

// ---------------- pass 2: recompute t1, mat1, mp1, t2 = fc2@[mat1;mp1], stats ----------------
__global__ void k2(const float* __restrict__ fc1, const float* __restrict__ fc2) {
    __shared__ float s_fc1[64];       // padded [ch][4]
    __shared__ float s_fc2[512];
    __shared__ float2 s_ab[16];
    __shared__ float s_red[8*32];
    int t = threadIdx.x, b = blockIdx.y;
    s_fc2[t] = fc2[t];
    s_fc2[t + 256] = fc2[t + 256];
    if (t < 16) {
        s_fc1[t*4+0] = fc1[t*3+0];
        s_fc1[t*4+1] = fc1[t*3+1];
        s_fc1[t*4+2] = fc1[t*3+2];
        s_fc1[t*4+3] = 0.0f;
        s_ab[t] = g_ab1[b*16 + t];
    }
    __syncthreads();

    int m = blockIdx.x * 16 + (t >> 4);
    int k = t & 15;
    float4 p = g_pts[(size_t)(b*M_ + m)*KNN + k];
    float dwk = g_dw[(size_t)(b*M_ + m)*KNN + k];

    float mat1[16], mp1[16];
    const float4* f1 = (const float4*)s_fc1;
    #pragma unroll
    for (int ch = 0; ch < 16; ch++) {
        float4 w = f1[ch];
        float v = w.x*p.x + w.y*p.y + w.z*p.z;
        float2 a = s_ab[ch];
        v = fmaxf(fmaf(v, a.x, a.y), 0.0f);
        mat1[ch] = v;
        float wmax = v * dwk;
        #pragma unroll
        for (int s = 8; s >= 1; s >>= 1) wmax = fmaxf(wmax, __shfl_xor_sync(0xffffffffu, wmax, s));
        mp1[ch] = wmax;
    }

    float t2v[16];
    const float4* f2 = (const float4*)s_fc2;
    #pragma unroll 4
    for (int j = 0; j < 16; j++) {
        float v = 0.0f;
        #pragma unroll
        for (int cq = 0; cq < 4; cq++) {
            float4 w = f2[j*8 + cq];
            v = fmaf(w.x, mat1[cq*4+0], v); v = fmaf(w.y, mat1[cq*4+1], v);
            v = fmaf(w.z, mat1[cq*4+2], v); v = fmaf(w.w, mat1[cq*4+3], v);
        }
        #pragma unroll
        for (int cq = 0; cq < 4; cq++) {
            float4 w = f2[j*8 + 4 + cq];
            v = fmaf(w.x, mp1[cq*4+0], v); v = fmaf(w.y, mp1[cq*4+1], v);
            v = fmaf(w.z, mp1[cq*4+2], v); v = fmaf(w.w, mp1[cq*4+3], v);
        }
        t2v[j] = v;
    }
    // store t2 layout [b][m][k][j]: 4 contiguous float4 per thread
    float4* o4 = (float4*)(g_t2 + (((size_t)(b*M_ + m)*16) + k)*16);
    o4[0] = make_float4(t2v[0], t2v[1], t2v[2], t2v[3]);
    o4[1] = make_float4(t2v[4], t2v[5], t2v[6], t2v[7]);
    o4[2] = make_float4(t2v[8], t2v[9], t2v[10], t2v[11]);
    o4[3] = make_float4(t2v[12], t2v[13], t2v[14], t2v[15]);

    float stat[32];
    #pragma unroll
    for (int j = 0; j < 16; j++) { stat[j] = t2v[j]; stat[16+j] = t2v[j]*t2v[j]; }
    int lane = t & 31, wid = t >> 5;
    #pragma unroll
    for (int i = 0; i < 32; i++) {
        float v = stat[i];
        #pragma unroll
        for (int s = 16; s >= 1; s >>= 1) v += __shfl_xor_sync(0xffffffffu, v, s);
        if (lane == 0) s_red[wid*32 + i] = v;
    }
    __syncthreads();
    if (t < 32) {
        float a = 0.0f;
        #pragma unroll
        for (int w = 0; w < 8; w++) a += s_red[w*32 + t];
        g_part2[((size_t)b*NBLK1 + blockIdx.x)*32 + t] = a;
    }
}

// ---------------- stats2: parallel reduction of 32 stats ----------------
__global__ void k_stats2(const float* __restrict__ bnw, const float* __restrict__ bnb) {
    __shared__ float s_p[32*32];
    __shared__ float s_c[32];
    int b = blockIdx.x, t = threadIdx.x;   // 1024 threads
    int w = t >> 5, s = t & 31;
    float a = 0.0f;
    #pragma unroll
    for (int i = 0; i < 16; i++)
        a += g_part2[((size_t)b*NBLK1 + w*16 + i)*32 + s];
    s_p[w*32 + s] = a;
    __syncthreads();
    if (t < 32) {
        float r = 0.0f;
        #pragma unroll
        for (int w2 = 0; w2 < 32; w2++) r += s_p[w2*32 + t];
        s_c[t] = r;
    }
    __syncthreads();
    if (t < 16) {
        float mean = s_c[t] * MK_INV;
        float var  = s_c[t+16] * MK_INV - mean*mean;
        float rstd = rsqrtf(var + 1e-5f);
        float sc = bnw[t] * rstd;
        g_ab2[b*16 + t] = make_float2(sc, bnb[t] - mean*sc);
    }
}

// ---------------- pass 3 (fused): mat3, gather+feat GEMM, cv GEMM ----------------
// 512 threads, 32 points per block.
// smem floats: s_feat 32*FS4*4=32896 | s_mat3 8192 | s_fc3 512 | s_ab 32 | s_idx 512i
#define K4_SMEM ((32896 + 8192 + 512 + 32 + 512) * 4)

__global__ void __launch_bounds__(512, 1)
k4(const int* __restrict__ nbr, const float* __restrict__ fc3, float* __restrict__ out) {
    extern __shared__ __align__(16) float sm[];
    float* s_feat = sm;                          // 32896 floats (32 rows x 1028)
    float* s_mat3 = sm + 32896;                  // 8192 (also reused as s_fin)
    float* s_fc3  = sm + 32896 + 8192;           // 512
    float* s_ab   = sm + 32896 + 8192 + 512;     // 32
    int*   s_idx  = (int*)(sm + 32896 + 8192 + 512 + 32); // 512

    int t = threadIdx.x, b = blockIdx.y;
    int m0 = blockIdx.x * 32;

    s_fc3[t] = fc3[t];
    s_idx[t] = nbr[((size_t)(b*M_) + m0)*KNN + t];
    if (t < 16) { float2 a = g_ab2[b*16 + t]; s_ab[t] = a.x; s_ab[16 + t] = a.y; }
    __syncthreads();

    // ---- phase 1: mat3[pt][k][j] ----
    {
        int pt = t >> 4, k = t & 15;
        int m = m0 + pt;
        float dwk = g_dw[(size_t)(b*M_ + m)*KNN + k];
        const float4* t24 = (const float4*)(g_t2 + (((size_t)(b*M_ + m)*16) + k)*16);
        float4 q0 = t24[0], q1 = t24[1], q2 = t24[2], q3 = t24[3];
        float mat2[16], mp2[16];
        mat2[0]=q0.x; mat2[1]=q0.y; mat2[2]=q0.z; mat2[3]=q0.w;
        mat2[4]=q1.x; mat2[5]=q1.y; mat2[6]=q1.z; mat2[7]=q1.w;
        mat2[8]=q2.x; mat2[9]=q2.y; mat2[10]=q2.z; mat2[11]=q2.w;
        mat2[12]=q3.x; mat2[13]=q3.y; mat2[14]=q3.z; mat2[15]=q3.w;
        #pragma unroll
        for (int ch = 0; ch < 16; ch++) {
            float v = fmaxf(fmaf(mat2[ch], s_ab[ch], s_ab[16 + ch]), 0.0f);
            mat2[ch] = v;
            float w = v * dwk;
            #pragma unroll
            for (int s = 8; s >= 1; s >>= 1) w = fmaxf(w, __shfl_xor_sync(0xffffffffu, w, s));
            mp2[ch] = w;
        }
        const float4* f3 = (const float4*)s_fc3;
        float t3[16];
        #pragma unroll 4
        for (int j = 0; j < 16; j++) {
            float v = 0.0f;
            #pragma unroll
            for (int cq = 0; cq < 4; cq++) {
                float4 w = f3[j*8 + cq];
                v = fmaf(w.x, mat2[cq*4+0], v); v = fmaf(w.y, mat2[cq*4+1], v);
                v = fmaf(w.z, mat2[cq*4+2], v); v = fmaf(w.w, mat2[cq*4+3], v);
            }
            #pragma unroll
            for (int cq = 0; cq < 4; cq++) {
                float4 w = f3[j*8 + 4 + cq];
                v = fmaf(w.x, mp2[cq*4+0], v); v = fmaf(w.y, mp2[cq*4+1], v);
                v = fmaf(w.z, mp2[cq*4+2], v); v = fmaf(w.w, mp2[cq*4+3], v);
            }
            t3[j] = fmaxf(v, 0.0f) * dwk;
        }
        float4* sm4 = (float4*)s_mat3;
        #pragma unroll
        for (int jg = 0; jg < 4; jg++)
            sm4[pt*64 + k*4 + jg] = make_float4(t3[jg*4], t3[jg*4+1], t3[jg*4+2], t3[jg*4+3]);
    }
    __syncthreads();

    // ---- phase 2: feat[pt][d = j*64 + c], packed f32x2 over j-pairs ----
    {
        int pt = t >> 4, cg = t & 15;           // 4 channels per thread
        ull facc2[4][8];
        #pragma unroll
        for (int i = 0; i < 4; i++)
            #pragma unroll
            for (int jp = 0; jp < 8; jp++) facc2[i][jp] = 0ull;

        const float4* xt4 = (const float4*)g_xt;
        const ulonglong2* sm2 = (const ulonglong2*)s_mat3;  // [pt][k][16 j] rows
        #pragma unroll 4
        for (int k = 0; k < 16; k++) {
            int n = s_idx[pt*16 + k];
            float4 xv = xt4[(size_t)(b*N_ + n)*16 + cg];
            ull d0 = dup2(xv.x), d1 = dup2(xv.y), d2 = dup2(xv.z), d3 = dup2(xv.w);
            ulonglong2 m0 = sm2[pt*64 + k*4 + 0];   // (j0,j1)(j2,j3)
            ulonglong2 m1 = sm2[pt*64 + k*4 + 1];   // (j4,j5)(j6,j7)
            ulonglong2 m2 = sm2[pt*64 + k*4 + 2];
            ulonglong2 m3 = sm2[pt*64 + k*4 + 3];
            facc2[0][0] = fma2(d0, m0.x, facc2[0][0]); facc2[1][0] = fma2(d1, m0.x, facc2[1][0]);
            facc2[2][0] = fma2(d2, m0.x, facc2[2][0]); facc2[3][0] = fma2(d3, m0.x, facc2[3][0]);
            facc2[0][1] = fma2(d0, m0.y, facc2[0][1]); facc2[1][1] = fma2(d1, m0.y, facc2[1][1]);
            facc2[2][1] = fma2(d2, m0.y, facc2[2][1]); facc2[3][1] = fma2(d3, m0.y, facc2[3][1]);
            facc2[0][2] = fma2(d0, m1.x, facc2[0][2]); facc2[1][2] = fma2(d1, m1.x, facc2[1][2]);
            facc2[2][2] = fma2(d2, m1.x, facc2[2][2]); facc2[3][2] = fma2(d3, m1.x, facc2[3][2]);
            facc2[0][3] = fma2(d0, m1.y, facc2[0][3]); facc2[1][3] = fma2(d1, m1.y, facc2[1][3]);
            facc2[2][3] = fma2(d2, m1.y, facc2[2][3]); facc2[3][3] = fma2(d3, m1.y, facc2[3][3]);
            facc2[0][4] = fma2(d0, m2.x, facc2[0][4]); facc2[1][4] = fma2(d1, m2.x, facc2[1][4]);
            facc2[2][4] = fma2(d2, m2.x, facc2[2][4]); facc2[3][4] = fma2(d3, m2.x, facc2[3][4]);
            facc2[0][5] = fma2(d0, m2.y, facc2[0][5]); facc2[1][5] = fma2(d1, m2.y, facc2[1][5]);
            facc2[2][5] = fma2(d2, m2.y, facc2[2][5]); facc2[3][5] = fma2(d3, m2.y, facc2[3][5]);
            facc2[0][6] = fma2(d0, m3.x, facc2[0][6]); facc2[1][6] = fma2(d1, m3.x, facc2[1][6]);
            facc2[2][6] = fma2(d2, m3.x, facc2[2][6]); facc2[3][6] = fma2(d3, m3.x, facc2[3][6]);
            facc2[0][7] = fma2(d0, m3.y, facc2[0][7]); facc2[1][7] = fma2(d1, m3.y, facc2[1][7]);
            facc2[2][7] = fma2(d2, m3.y, facc2[2][7]); facc2[3][7] = fma2(d3, m3.y, facc2[3][7]);
        }
        // store feat[pt][j*16+cg] float4 = (c0..c3 at fixed j); unpack is register aliasing
        float4* sf4 = (float4*)s_feat;
        #pragma unroll
        for (int jp = 0; jp < 8; jp++) {
            float2 a0 = unpack2(facc2[0][jp]);
            float2 a1 = unpack2(facc2[1][jp]);
            float2 a2 = unpack2(facc2[2][jp]);
            float2 a3 = unpack2(facc2[3][jp]);
            sf4[pt*FS4 + (2*jp)  *16 + cg] = make_float4(a0.x, a1.x, a2.x, a3.x);
            sf4[pt*FS4 + (2*jp+1)*16 + cg] = make_float4(a0.y, a1.y, a2.y, a3.y);
        }
    }
    __syncthreads();

    // ---- phase 3: out[o][p] = dot(cv2[o], feat[p]) over d=1024, lane-over-d, f32x2 ----
    {
        int warp = t >> 5, lane = t & 31;
        int g    = warp >> 2;                   // o group base
        int pbase = (warp & 3) * 8;             // 8 points per warp
        const ulonglong2* cv2 = (const ulonglong2*)g_cvP;
        const ulonglong2* sf2 = (const ulonglong2*)s_feat;
        float* s_fin = s_mat3;                  // reuse: [o][p] 64x32

        #pragma unroll 1
        for (int it = 0; it < 4; it++) {
            int obase = g*4 + it*16;
            ull acc[4][8];
            #pragma unroll
            for (int oi = 0; oi < 4; oi++)
                #pragma unroll
                for (int pi = 0; pi < 8; pi++) acc[oi][pi] = 0ull;

            #pragma unroll 2
            for (int s = 0; s < 8; s++) {
                ulonglong2 wv[4], fv[8];
                #pragma unroll
                for (int oi = 0; oi < 4; oi++)
                    wv[oi] = cv2[(obase + oi)*256 + s*32 + lane];
                #pragma unroll
                for (int pi = 0; pi < 8; pi++)
                    fv[pi] = sf2[(pbase + pi)*FS4 + s*32 + lane];
                #pragma unroll
                for (int oi = 0; oi < 4; oi++)
                    #pragma unroll
                    for (int pi = 0; pi < 8; pi++) {
                        acc[oi][pi] = fma2(wv[oi].x, fv[pi].x, acc[oi][pi]);
                        acc[oi][pi] = fma2(wv[oi].y, fv[pi].y, acc[oi][pi]);
                    }
            }
            // reduce: add packed halves, then 5-level butterfly, one lane stores
            #pragma unroll
            for (int oi = 0; oi < 4; oi++)
                #pragma unroll
                for (int pi = 0; pi < 8; pi++) {
                    float2 h = unpack2(acc[oi][pi]);
                    float v = h.x + h.y;
                    #pragma unroll
                    for (int s = 16; s >= 1; s >>= 1) v += __shfl_xor_sync(0xffffffffu, v, s);
                    if (lane == oi*8 + pi)
                        s_fin[(obase + oi)*32 + pbase + pi] = v;
                }
        }
    }
    __syncthreads();

    // coalesced output write
    {
        int o = t >> 3, pq = t & 7;
        float4 v = ((const float4*)s_mat3)[o*8 + pq];
        ((float4*)out)[((size_t)(b*64 + o))*2048 + (m0 >> 2) + pq] = v;
    }
}

// ---------------- launch ----------------
extern "C" void kernel_launch(void* const* d_in, const int* in_sizes, int n_in,
                              void* d_out, int out_size) {
    const float* x     = (const float*)d_in[0];
    const float* pos   = (const float*)d_in[1];
    const float* sup   = (const float*)d_in[2];
    const int*   nbr   = (const int*)  d_in[3];
    const float* alpha = (const float*)d_in[4];
    const float* beta  = (const float*)d_in[5];
    const float* nr    = (const float*)d_in[6];
    const float* fc1   = (const float*)d_in[7];
    const float* fc2   = (const float*)d_in[8];
    const float* fc3   = (const float*)d_in[9];
    const float* bn1w  = (const float*)d_in[10];
    const float* bn1b  = (const float*)d_in[11];
    const float* bn2w  = (const float*)d_in[12];
    const float* bn2b  = (const float*)d_in[13];
    const float* cvw   = (const float*)d_in[14];
    float* out = (float*)d_out;

    cudaFuncSetAttribute((const void*)k4, cudaFuncAttributeMaxDynamicSharedMemorySize, K4_SMEM);

    k_xt    <<<dim3(N_/32, C_/32, B_), dim3(32, 8)>>>(x);
    k_pos   <<<dim3(N_/256, B_), 256>>>(pos);
    k_cvp   <<<256, 256>>>(cvw);
    k1      <<<dim3(NBLK1, B_), 256>>>(sup, nbr, alpha, beta, nr);
    k_stats1<<<B_, 512>>>(fc1, bn1w, bn1b);
    k2      <<<dim3(NBLK1, B_), 256>>>(fc1, fc2);
    k_stats2<<<B_, 1024>>>(bn2w, bn2b);
    k4      <<<dim3(M_/32, B_), 512, K4_SMEM>>>(nbr, fc3, out);
}

// round 8
// speedup vs baseline: 1.2347x; 1.0234x over previous
#include <cuda_runtime.h>
#include <stdint.h>
#include <math.h>

// Problem constants (fixed by setup_inputs)
#define B_   4
#define N_   8192
#define M_   8192
#define KNN  16
#define C_   64
#define NBLK1 512
#define MK_INV (1.0f/((float)M_*(float)KNN))
#define FS4  257   // padded feat row stride in float4 (1028 floats)
#define PTS_ 16    // points per k4 block

typedef unsigned long long ull;

// ---------------- packed f32x2 helpers (Blackwell base ISA) ----------------
__device__ __forceinline__ ull fma2(ull a, ull b, ull c) {
    ull d;
    asm("fma.rn.f32x2 %0, %1, %2, %3;" : "=l"(d) : "l"(a), "l"(b), "l"(c));
    return d;
}
__device__ __forceinline__ ull dup2(float x) {
    ull r;
    asm("mov.b64 %0, {%1, %2};" : "=l"(r) : "f"(x), "f"(x));
    return r;
}
__device__ __forceinline__ float2 unpack2(ull v) {
    float2 f;
    asm("mov.b64 {%0, %1}, %2;" : "=f"(f.x), "=f"(f.y) : "l"(v));
    return f;
}

// ---------------- device scratch ----------------
__device__ float  g_xt  [B_*N_*C_];        // x transposed: [B][N][64]
__device__ float  g_post[B_*N_*4];         // pos transposed+padded
__device__ float4 g_pts [B_*M_*KNN];       // normalized pts per neighbor
__device__ float  g_dw  [B_*M_*KNN];       // distance weights
__device__ float  g_t2  [(size_t)B_*M_*256]; // fc2 out, layout [b][m][k][j]
__device__ float  g_part1[B_*NBLK1*16];
__device__ float  g_part2[B_*NBLK1*32];
__device__ float2 g_ab1[B_*16];
__device__ float2 g_ab2[B_*16];
__device__ __align__(16) float g_cvP[64*1024];  // cv repacked [o][d], d=j*64+c

// ---------------- prep kernels ----------------
__global__ void k_xt(const float* __restrict__ x) {
    __shared__ float tile[32][33];
    int b  = blockIdx.z;
    int c0 = blockIdx.y * 32;
    int n0 = blockIdx.x * 32;
    int tx = threadIdx.x, ty = threadIdx.y;   // 32 x 8
    #pragma unroll
    for (int i = 0; i < 32; i += 8)
        tile[ty + i][tx] = x[(size_t)(b*C_ + c0 + ty + i)*N_ + n0 + tx];
    __syncthreads();
    #pragma unroll
    for (int i = 0; i < 32; i += 8)
        g_xt[(size_t)(b*N_ + n0 + ty + i)*C_ + c0 + tx] = tile[tx][ty + i];
}

__global__ void k_pos(const float* __restrict__ pos) {
    int b = blockIdx.y;
    int n = blockIdx.x * 256 + threadIdx.x;
    float4 v;
    v.x = pos[(size_t)(b*3 + 0)*N_ + n];
    v.y = pos[(size_t)(b*3 + 1)*N_ + n];
    v.z = pos[(size_t)(b*3 + 2)*N_ + n];
    v.w = 0.0f;
    ((float4*)g_post)[b*N_ + n] = v;
}

// cv2[o][d] with d = j*64 + c
__global__ void k_cvp(const float* __restrict__ cv) {
    int g = blockIdx.x * 256 + threadIdx.x;  // 65536
    int o = g >> 10;
    int d = g & 1023;
    int c = d & 63;
    int j = d >> 6;
    g_cvP[g] = cv[(size_t)(o*64 + c)*16 + j];
}

// ---------------- pass 1: pts, dw, 9 raw moments ----------------
__global__ void k1(const float* __restrict__ sup, const int* __restrict__ nbr,
                   const float* __restrict__ alpha_p, const float* __restrict__ beta_p,
                   const float* __restrict__ nr_p) {
    __shared__ float s_red[8*9];
    int t = threadIdx.x;
    int b = blockIdx.y;
    int m = blockIdx.x * 16 + (t >> 4);
    int k = t & 15;
    float alpha = alpha_p[0], beta = beta_p[0], inr = 1.0f / nr_p[0];

    int n = nbr[(size_t)(b*M_ + m)*KNN + k];
    float4 p = ((const float4*)g_post)[b*N_ + n];
    float sx = sup[(size_t)(b*3 + 0)*M_ + m];
    float sy = sup[(size_t)(b*3 + 1)*M_ + m];
    float sz = sup[(size_t)(b*3 + 2)*M_ + m];
    float px = p.x - sx, py = p.y - sy, pz = p.z - sz;

    float d  = sqrtf(px*px + py*py + pz*pz);
    float sg = 1.0f / (1.0f + expf(alpha*d - beta));
    float ssum = sg;
    #pragma unroll
    for (int s = 8; s >= 1; s >>= 1) ssum += __shfl_xor_sync(0xffffffffu, ssum, s);
    float dws = ssum + ((ssum == 0.0f) ? 1.0f : 0.0f) + 1e-6f;
    float dwk = sg / dws * (float)KNN;
    g_dw[(size_t)(b*M_ + m)*KNN + k] = dwk;

    px *= inr; py *= inr; pz *= inr;
    g_pts[(size_t)(b*M_ + m)*KNN + k] = make_float4(px, py, pz, 0.0f);

    float mom[9];
    mom[0]=px; mom[1]=py; mom[2]=pz;
    mom[3]=px*px; mom[4]=py*py; mom[5]=pz*pz;
    mom[6]=px*py; mom[7]=px*pz; mom[8]=py*pz;

    int lane = t & 31, wid = t >> 5;
    #pragma unroll
    for (int i = 0; i < 9; i++) {
        float v = mom[i];
        #pragma unroll
        for (int s = 16; s >= 1; s >>= 1) v += __shfl_xor_sync(0xffffffffu, v, s);
        if (lane == 0) s_red[wid*9 + i] = v;
    }
    __syncthreads();
    if (t < 9) {
        float a = 0.0f;
        #pragma unroll
        for (int w = 0; w < 8; w++) a += s_red[w*9 + t];
        g_part1[((size_t)b*NBLK1 + blockIdx.x)*16 + t] = a;
    }
}

// ---------------- stats1: analytic per-channel mean/var from moments ----------------
__global__ void k_stats1(const float* __restrict__ fc1,
                         const float* __restrict__ bnw, const float* __restrict__ bnb) {
    __shared__ float s_w[16];
    __shared__ float s_m[9];
    int b = blockIdx.x, t = threadIdx.x;   // 512 threads
    int lane = t & 31, wid = t >> 5;
    float v[9];
    #pragma unroll
    for (int i = 0; i < 9; i++) v[i] = g_part1[((size_t)b*NBLK1 + t)*16 + i];
    #pragma unroll
    for (int i = 0; i < 9; i++) {
        float r = v[i];
        #pragma unroll
        for (int s = 16; s >= 1; s >>= 1) r += __shfl_xor_sync(0xffffffffu, r, s);
        if (lane == 0) s_w[wid] = r;
        __syncthreads();
        if (t == 0) {
            float a = 0.0f;
            #pragma unroll
            for (int w = 0; w < 16; w++) a += s_w[w];
            s_m[i] = a * MK_INV;
        }
        __syncthreads();
    }
    if (t < 16) {
        float w0 = fc1[t*3], w1 = fc1[t*3+1], w2 = fc1[t*3+2];
        float mean = w0*s_m[0] + w1*s_m[1] + w2*s_m[2];
        float ev2  = w0*w0*s_m[3] + w1*w1*s_m[4] + w2*w2*s_m[5]
                   + 2.0f*(w0*w1*s_m[6] + w0*w2*s_m[7] + w1*w2*s_m[8]);
        float var  = ev2 - mean*mean;
        float rstd = rsqrtf(var + 1e-5f);
        float sc = bnw[t] * rstd;
        g_ab1[b*16 + t] = make_float2(sc, bnb[t] - mean*sc);
    }
}

// ---------------- pass 2: recompute t1, mat1, mp1, t2 = fc2@[mat1;mp1], stats ----------------
__global__ void k2(const float* __restrict__ fc1, const float* __restrict__ fc2) {
    __shared__ float s_fc1[64];       // padded [ch][4]
    __shared__ float s_fc2[512];
    __shared__ float2 s_ab[16];
    __shared__ float s_red[8*32];
    int t = threadIdx.x, b = blockIdx.y;
    s_fc2[t] = fc2[t];
    s_fc2[t + 256] = fc2[t + 256];
    if (t < 16) {
        s_fc1[t*4+0] = fc1[t*3+0];
        s_fc1[t*4+1] = fc1[t*3+1];
        s_fc1[t*4+2] = fc1[t*3+2];
        s_fc1[t*4+3] = 0.0f;
        s_ab[t] = g_ab1[b*16 + t];
    }
    __syncthreads();

    int m = blockIdx.x * 16 + (t >> 4);
    int k = t & 15;
    float4 p = g_pts[(size_t)(b*M_ + m)*KNN + k];
    float dwk = g_dw[(size_t)(b*M_ + m)*KNN + k];

    float mat1[16], mp1[16];
    const float4* f1 = (const float4*)s_fc1;
    #pragma unroll
    for (int ch = 0; ch < 16; ch++) {
        float4 w = f1[ch];
        float v = w.x*p.x + w.y*p.y + w.z*p.z;
        float2 a = s_ab[ch];
        v = fmaxf(fmaf(v, a.x, a.y), 0.0f);
        mat1[ch] = v;
        float wmax = v * dwk;
        #pragma unroll
        for (int s = 8; s >= 1; s >>= 1) wmax = fmaxf(wmax, __shfl_xor_sync(0xffffffffu, wmax, s));
        mp1[ch] = wmax;
    }

    float t2v[16];
    const float4* f2 = (const float4*)s_fc2;
    #pragma unroll 4
    for (int j = 0; j < 16; j++) {
        float v = 0.0f;
        #pragma unroll
        for (int cq = 0; cq < 4; cq++) {
            float4 w = f2[j*8 + cq];
            v = fmaf(w.x, mat1[cq*4+0], v); v = fmaf(w.y, mat1[cq*4+1], v);
            v = fmaf(w.z, mat1[cq*4+2], v); v = fmaf(w.w, mat1[cq*4+3], v);
        }
        #pragma unroll
        for (int cq = 0; cq < 4; cq++) {
            float4 w = f2[j*8 + 4 + cq];
            v = fmaf(w.x, mp1[cq*4+0], v); v = fmaf(w.y, mp1[cq*4+1], v);
            v = fmaf(w.z, mp1[cq*4+2], v); v = fmaf(w.w, mp1[cq*4+3], v);
        }
        t2v[j] = v;
    }
    // store t2 layout [b][m][k][j]: 4 contiguous float4 per thread
    float4* o4 = (float4*)(g_t2 + (((size_t)(b*M_ + m)*16) + k)*16);
    o4[0] = make_float4(t2v[0], t2v[1], t2v[2], t2v[3]);
    o4[1] = make_float4(t2v[4], t2v[5], t2v[6], t2v[7]);
    o4[2] = make_float4(t2v[8], t2v[9], t2v[10], t2v[11]);
    o4[3] = make_float4(t2v[12], t2v[13], t2v[14], t2v[15]);

    float stat[32];
    #pragma unroll
    for (int j = 0; j < 16; j++) { stat[j] = t2v[j]; stat[16+j] = t2v[j]*t2v[j]; }
    int lane = t & 31, wid = t >> 5;
    #pragma unroll
    for (int i = 0; i < 32; i++) {
        float v = stat[i];
        #pragma unroll
        for (int s = 16; s >= 1; s >>= 1) v += __shfl_xor_sync(0xffffffffu, v, s);
        if (lane == 0) s_red[wid*32 + i] = v;
    }
    __syncthreads();
    if (t < 32) {
        float a = 0.0f;
        #pragma unroll
        for (int w = 0; w < 8; w++) a += s_red[w*32 + t];
        g_part2[((size_t)b*NBLK1 + blockIdx.x)*32 + t] = a;
    }
}

// ---------------- stats2: parallel reduction of 32 stats ----------------
__global__ void k_stats2(const float* __restrict__ bnw, const float* __restrict__ bnb) {
    __shared__ float s_p[32*32];
    __shared__ float s_c[32];
    int b = blockIdx.x, t = threadIdx.x;   // 1024 threads
    int w = t >> 5, s = t & 31;
    float a = 0.0f;
    #pragma unroll
    for (int i = 0; i < 16; i++)
        a += g_part2[((size_t)b*NBLK1 + w*16 + i)*32 + s];
    s_p[w*32 + s] = a;
    __syncthreads();
    if (t < 32) {
        float r = 0.0f;
        #pragma unroll
        for (int w2 = 0; w2 < 32; w2++) r += s_p[w2*32 + t];
        s_c[t] = r;
    }
    __syncthreads();
    if (t < 16) {
        float mean = s_c[t] * MK_INV;
        float var  = s_c[t+16] * MK_INV - mean*mean;
        float rstd = rsqrtf(var + 1e-5f);
        float sc = bnw[t] * rstd;
        g_ab2[b*16 + t] = make_float2(sc, bnb[t] - mean*sc);
    }
}

// ---------------- pass 3 (fused): mat3, gather+feat GEMM, cv GEMM ----------------
// 256 threads, 16 points per block, 2 CTAs/SM.
// smem floats: s_feat 16*FS4*4=16448 | s_mat3 4096 | s_fc3 512 | s_ab 32 | s_idx 256i
#define K4_SMEM ((16448 + 4096 + 512 + 32 + 256) * 4)

__global__ void __launch_bounds__(256, 2)
k4(const int* __restrict__ nbr, const float* __restrict__ fc3, float* __restrict__ out) {
    extern __shared__ __align__(16) float sm[];
    float* s_feat = sm;                          // 16448 floats (16 rows x 1028)
    float* s_mat3 = sm + 16448;                  // 4096 (also reused as s_fin)
    float* s_fc3  = sm + 16448 + 4096;           // 512
    float* s_ab   = sm + 16448 + 4096 + 512;     // 32
    int*   s_idx  = (int*)(sm + 16448 + 4096 + 512 + 32); // 256

    int t = threadIdx.x, b = blockIdx.y;
    int m0 = blockIdx.x * PTS_;

    s_fc3[t] = fc3[t];
    s_fc3[t + 256] = fc3[t + 256];
    s_idx[t] = nbr[((size_t)(b*M_) + m0)*KNN + t];
    if (t < 16) { float2 a = g_ab2[b*16 + t]; s_ab[t] = a.x; s_ab[16 + t] = a.y; }
    __syncthreads();

    // ---- phase 1: mat3[pt][k][j] ----
    {
        int pt = t >> 4, k = t & 15;
        int m = m0 + pt;
        float dwk = g_dw[(size_t)(b*M_ + m)*KNN + k];
        const float4* t24 = (const float4*)(g_t2 + (((size_t)(b*M_ + m)*16) + k)*16);
        float4 q0 = t24[0], q1 = t24[1], q2 = t24[2], q3 = t24[3];
        float mat2[16], mp2[16];
        mat2[0]=q0.x; mat2[1]=q0.y; mat2[2]=q0.z; mat2[3]=q0.w;
        mat2[4]=q1.x; mat2[5]=q1.y; mat2[6]=q1.z; mat2[7]=q1.w;
        mat2[8]=q2.x; mat2[9]=q2.y; mat2[10]=q2.z; mat2[11]=q2.w;
        mat2[12]=q3.x; mat2[13]=q3.y; mat2[14]=q3.z; mat2[15]=q3.w;
        #pragma unroll
        for (int ch = 0; ch < 16; ch++) {
            float v = fmaxf(fmaf(mat2[ch], s_ab[ch], s_ab[16 + ch]), 0.0f);
            mat2[ch] = v;
            float w = v * dwk;
            #pragma unroll
            for (int s = 8; s >= 1; s >>= 1) w = fmaxf(w, __shfl_xor_sync(0xffffffffu, w, s));
            mp2[ch] = w;
        }
        const float4* f3 = (const float4*)s_fc3;
        float t3[16];
        #pragma unroll 4
        for (int j = 0; j < 16; j++) {
            float v = 0.0f;
            #pragma unroll
            for (int cq = 0; cq < 4; cq++) {
                float4 w = f3[j*8 + cq];
                v = fmaf(w.x, mat2[cq*4+0], v); v = fmaf(w.y, mat2[cq*4+1], v);
                v = fmaf(w.z, mat2[cq*4+2], v); v = fmaf(w.w, mat2[cq*4+3], v);
            }
            #pragma unroll
            for (int cq = 0; cq < 4; cq++) {
                float4 w = f3[j*8 + 4 + cq];
                v = fmaf(w.x, mp2[cq*4+0], v); v = fmaf(w.y, mp2[cq*4+1], v);
                v = fmaf(w.z, mp2[cq*4+2], v); v = fmaf(w.w, mp2[cq*4+3], v);
            }
            t3[j] = fmaxf(v, 0.0f) * dwk;
        }
        float4* sm4 = (float4*)s_mat3;
        #pragma unroll
        for (int jg = 0; jg < 4; jg++)
            sm4[pt*64 + k*4 + jg] = make_float4(t3[jg*4], t3[jg*4+1], t3[jg*4+2], t3[jg*4+3]);
    }
    __syncthreads();

    // ---- phase 2: feat[pt][d = j*64 + c], packed f32x2 over j-pairs ----
    {
        int pt = t >> 4, cg = t & 15;           // 4 channels per thread
        ull facc2[4][8];
        #pragma unroll
        for (int i = 0; i < 4; i++)
            #pragma unroll
            for (int jp = 0; jp < 8; jp++) facc2[i][jp] = 0ull;

        const float4* xt4 = (const float4*)g_xt;
        const ulonglong2* sm2 = (const ulonglong2*)s_mat3;  // [pt][k][16 j] rows
        #pragma unroll 4
        for (int k = 0; k < 16; k++) {
            int n = s_idx[pt*16 + k];
            float4 xv = xt4[(size_t)(b*N_ + n)*16 + cg];
            ull d0 = dup2(xv.x), d1 = dup2(xv.y), d2 = dup2(xv.z), d3 = dup2(xv.w);
            ulonglong2 m0v = sm2[pt*64 + k*4 + 0];   // (j0,j1)(j2,j3)
            ulonglong2 m1v = sm2[pt*64 + k*4 + 1];   // (j4,j5)(j6,j7)
            ulonglong2 m2v = sm2[pt*64 + k*4 + 2];
            ulonglong2 m3v = sm2[pt*64 + k*4 + 3];
            facc2[0][0] = fma2(d0, m0v.x, facc2[0][0]); facc2[1][0] = fma2(d1, m0v.x, facc2[1][0]);
            facc2[2][0] = fma2(d2, m0v.x, facc2[2][0]); facc2[3][0] = fma2(d3, m0v.x, facc2[3][0]);
            facc2[0][1] = fma2(d0, m0v.y, facc2[0][1]); facc2[1][1] = fma2(d1, m0v.y, facc2[1][1]);
            facc2[2][1] = fma2(d2, m0v.y, facc2[2][1]); facc2[3][1] = fma2(d3, m0v.y, facc2[3][1]);
            facc2[0][2] = fma2(d0, m1v.x, facc2[0][2]); facc2[1][2] = fma2(d1, m1v.x, facc2[1][2]);
            facc2[2][2] = fma2(d2, m1v.x, facc2[2][2]); facc2[3][2] = fma2(d3, m1v.x, facc2[3][2]);
            facc2[0][3] = fma2(d0, m1v.y, facc2[0][3]); facc2[1][3] = fma2(d1, m1v.y, facc2[1][3]);
            facc2[2][3] = fma2(d2, m1v.y, facc2[2][3]); facc2[3][3] = fma2(d3, m1v.y, facc2[3][3]);
            facc2[0][4] = fma2(d0, m2v.x, facc2[0][4]); facc2[1][4] = fma2(d1, m2v.x, facc2[1][4]);
            facc2[2][4] = fma2(d2, m2v.x, facc2[2][4]); facc2[3][4] = fma2(d3, m2v.x, facc2[3][4]);
            facc2[0][5] = fma2(d0, m2v.y, facc2[0][5]); facc2[1][5] = fma2(d1, m2v.y, facc2[1][5]);
            facc2[2][5] = fma2(d2, m2v.y, facc2[2][5]); facc2[3][5] = fma2(d3, m2v.y, facc2[3][5]);
            facc2[0][6] = fma2(d0, m3v.x, facc2[0][6]); facc2[1][6] = fma2(d1, m3v.x, facc2[1][6]);
            facc2[2][6] = fma2(d2, m3v.x, facc2[2][6]); facc2[3][6] = fma2(d3, m3v.x, facc2[3][6]);
            facc2[0][7] = fma2(d0, m3v.y, facc2[0][7]); facc2[1][7] = fma2(d1, m3v.y, facc2[1][7]);
            facc2[2][7] = fma2(d2, m3v.y, facc2[2][7]); facc2[3][7] = fma2(d3, m3v.y, facc2[3][7]);
        }
        float4* sf4 = (float4*)s_feat;
        #pragma unroll
        for (int jp = 0; jp < 8; jp++) {
            float2 a0 = unpack2(facc2[0][jp]);
            float2 a1 = unpack2(facc2[1][jp]);
            float2 a2 = unpack2(facc2[2][jp]);
            float2 a3 = unpack2(facc2[3][jp]);
            sf4[pt*FS4 + (2*jp)  *16 + cg] = make_float4(a0.x, a1.x, a2.x, a3.x);
            sf4[pt*FS4 + (2*jp+1)*16 + cg] = make_float4(a0.y, a1.y, a2.y, a3.y);
        }
    }
    __syncthreads();

    // ---- phase 3: out[o][p] = dot(cv2[o], feat[p]) over d=1024, lane-over-d, f32x2 ----
    {
        int warp = t >> 5, lane = t & 31;
        int g    = warp >> 1;                   // o group 0..3
        int pbase = (warp & 1) * 8;             // 8 points per warp
        const ulonglong2* cv2 = (const ulonglong2*)g_cvP;
        const ulonglong2* sf2 = (const ulonglong2*)s_feat;
        float* s_fin = s_mat3;                  // reuse: [o][p] 64x16

        #pragma unroll 1
        for (int it = 0; it < 4; it++) {
            int obase = g*4 + it*16;
            ull acc[4][8];
            #pragma unroll
            for (int oi = 0; oi < 4; oi++)
                #pragma unroll
                for (int pi = 0; pi < 8; pi++) acc[oi][pi] = 0ull;

            #pragma unroll 2
            for (int s = 0; s < 8; s++) {
                ulonglong2 wv[4], fv[8];
                #pragma unroll
                for (int oi = 0; oi < 4; oi++)
                    wv[oi] = cv2[(obase + oi)*256 + s*32 + lane];
                #pragma unroll
                for (int pi = 0; pi < 8; pi++)
                    fv[pi] = sf2[(pbase + pi)*FS4 + s*32 + lane];
                #pragma unroll
                for (int oi = 0; oi < 4; oi++)
                    #pragma unroll
                    for (int pi = 0; pi < 8; pi++) {
                        acc[oi][pi] = fma2(wv[oi].x, fv[pi].x, acc[oi][pi]);
                        acc[oi][pi] = fma2(wv[oi].y, fv[pi].y, acc[oi][pi]);
                    }
            }
            // reduce: add packed halves, then 5-level butterfly, one lane stores
            #pragma unroll
            for (int oi = 0; oi < 4; oi++)
                #pragma unroll
                for (int pi = 0; pi < 8; pi++) {
                    float2 h = unpack2(acc[oi][pi]);
                    float v = h.x + h.y;
                    #pragma unroll
                    for (int s = 16; s >= 1; s >>= 1) v += __shfl_xor_sync(0xffffffffu, v, s);
                    if (lane == oi*8 + pi)
                        s_fin[(obase + oi)*16 + pbase + pi] = v;
                }
        }
    }
    __syncthreads();

    // coalesced output write: 64 o x 16 p = 1024 floats, 256 threads x float4
    {
        int o = t >> 2, pq = t & 3;
        float4 v = ((const float4*)s_mat3)[o*4 + pq];
        ((float4*)out)[((size_t)(b*64 + o))*2048 + (m0 >> 2) + pq] = v;
    }
}

// ---------------- launch ----------------
extern "C" void kernel_launch(void* const* d_in, const int* in_sizes, int n_in,
                              void* d_out, int out_size) {
    const float* x     = (const float*)d_in[0];
    const float* pos   = (const float*)d_in[1];
    const float* sup   = (const float*)d_in[2];
    const int*   nbr   = (const int*)  d_in[3];
    const float* alpha = (const float*)d_in[4];
    const float* beta  = (const float*)d_in[5];
    const float* nr    = (const float*)d_in[6];
    const float* fc1   = (const float*)d_in[7];
    const float* fc2   = (const float*)d_in[8];
    const float* fc3   = (const float*)d_in[9];
    const float* bn1w  = (const float*)d_in[10];
    const float* bn1b  = (const float*)d_in[11];
    const float* bn2w  = (const float*)d_in[12];
    const float* bn2b  = (const float*)d_in[13];
    const float* cvw   = (const float*)d_in[14];
    float* out = (float*)d_out;

    cudaFuncSetAttribute((const void*)k4, cudaFuncAttributeMaxDynamicSharedMemorySize, K4_SMEM);

    k_xt    <<<dim3(N_/32, C_/32, B_), dim3(32, 8)>>>(x);
    k_pos   <<<dim3(N_/256, B_), 256>>>(pos);
    k_cvp   <<<256, 256>>>(cvw);
    k1      <<<dim3(NBLK1, B_), 256>>>(sup, nbr, alpha, beta, nr);
    k_stats1<<<B_, 512>>>(fc1, bn1w, bn1b);
    k2      <<<dim3(NBLK1, B_), 256>>>(fc1, fc2);
    k_stats2<<<B_, 1024>>>(bn2w, bn2b);
    k4      <<<dim3(M_/PTS_, B_), 256, K4_SMEM>>>(nbr, fc3, out);
}